// round 9
// baseline (speedup 1.0000x reference)
#include <cuda_runtime.h>
#include <cstdint>
#include <math.h>

#define B_ 16
#define S_ 4096
#define DQ_ 1024
#define DM_ 512
#define DO_ 1024
#define H_ 16
#define D_ 64

typedef unsigned long long u64;

// -------- scratch (no allocs allowed) --------
__device__ float g_q[B_ * DO_];          // scaled query projections [b][h*64+d]
__device__ float g_ut[B_ * DM_ * H_];    // folded key proj, TRANSPOSED: [b][m][h]
__device__ float g_c[B_ * H_ * DM_];     // attn-weighted mb sums [b][h][m]
__device__ float g_Z[B_ * H_];           // softmax denominators

// -------- packed fp32x2 helpers --------
__device__ __forceinline__ u64 pack2(float lo, float hi) {
    u64 r; asm("mov.b64 %0, {%1,%2};" : "=l"(r) : "f"(lo), "f"(hi)); return r;
}
__device__ __forceinline__ void unpack2(u64 v, float& lo, float& hi) {
    asm("mov.b64 {%0,%1}, %2;" : "=f"(lo), "=f"(hi) : "l"(v));
}
__device__ __forceinline__ void ffma2(u64& d, u64 a, u64 b) {
    asm("fma.rn.f32x2 %0, %1, %2, %3;" : "=l"(d) : "l"(a), "l"(b), "l"(d));
}

// ============================================================
// Kernel 0: zero accumulators. grid 512, block 256
// ============================================================
__global__ __launch_bounds__(256) void k_zero(float* __restrict__ out) {
    int i = blockIdx.x * 256 + threadIdx.x;
    if (i < B_ * DO_) { g_q[i] = 0.f; out[i] = 0.f; }
    if (i < B_ * H_ * DM_) g_c[i] = 0.f;
    if (i < B_ * H_) g_Z[i] = 0.f;
}

// ============================================================
// Kernel 1: q partial, Wq read once. grid (4,16), block 256
// ============================================================
__global__ __launch_bounds__(256) void k_qproj(const float* __restrict__ src,
                                               const float* __restrict__ Wq) {
    __shared__ float s_src[B_][64];
    int t = threadIdx.x;
    int o = blockIdx.x * 256 + t;
    int k0 = blockIdx.y * 64;
#pragma unroll
    for (int i = 0; i < 4; ++i) {
        int idx = i * 256 + t;
        s_src[idx >> 6][idx & 63] = src[(size_t)(idx >> 6) * DQ_ + k0 + (idx & 63)];
    }
    __syncthreads();
    float acc[B_];
#pragma unroll
    for (int b = 0; b < B_; ++b) acc[b] = 0.f;
#pragma unroll 4
    for (int k = 0; k < 64; ++k) {
        float wq = Wq[(size_t)(k0 + k) * DO_ + o];
#pragma unroll
        for (int b = 0; b < B_; ++b) acc[b] = fmaf(s_src[b][k], wq, acc[b]);
    }
#pragma unroll
    for (int b = 0; b < B_; ++b) atomicAdd(&g_q[b * DO_ + o], acc[b] * 0.125f);
}

// ============================================================
// Kernel 2: u[b,h,m] = sum_d Wk[m,h*64+d]*q[b,h,d], stored [b][m][h]
// grid B*H, block 256
// ============================================================
__global__ __launch_bounds__(256) void k_uproj(const float* __restrict__ Wk) {
    int bh = blockIdx.x;
    int b = bh >> 4, h = bh & 15;
    __shared__ float s_q[D_];
    if (threadIdx.x < D_) s_q[threadIdx.x] = g_q[b * DO_ + h * D_ + threadIdx.x];
    __syncthreads();
    for (int m = threadIdx.x; m < DM_; m += 256) {
        const float4* w = reinterpret_cast<const float4*>(Wk + (size_t)m * DO_ + h * D_);
        float acc = 0.f;
#pragma unroll
        for (int d4 = 0; d4 < D_ / 4; ++d4) {
            float4 wv = w[d4];
            acc = fmaf(wv.x, s_q[d4 * 4 + 0], acc);
            acc = fmaf(wv.y, s_q[d4 * 4 + 1], acc);
            acc = fmaf(wv.z, s_q[d4 * 4 + 2], acc);
            acc = fmaf(wv.w, s_q[d4 * 4 + 3], acc);
        }
        g_ut[((size_t)b * DM_ + m) * H_ + h] = acc;
    }
}

// ============================================================
// Kernel 3: e[b,h,s] = exp(score), masked->0, Z accumulated.
// TS=64, block 128, thread = 1 s x 8 h. grid (64, B) = 1024 CTAs.
// Static smem ~10.5KB.
// ============================================================
#define TS3 64
#define KC3 32
__global__ __launch_bounds__(128) void k_scores(const float* __restrict__ mb,
                                                float* __restrict__ attn,
                                                const int* __restrict__ mask) {
    __shared__ float mb_s[TS3][KC3 + 1];     // pitch 33, conflict-free
    __shared__ __align__(16) float u_s[KC3][H_];
    __shared__ float s_Z[H_];

    int b = blockIdx.y, s_tile = blockIdx.x * TS3;
    int t = threadIdx.x, w = t >> 5, l = t & 31;
    int s_loc = w * 16 + (l & 15);           // this thread's single s
    int h0 = (l >> 4) * 8;                   // 8 heads: h0..h0+7

    u64 acc[4];
#pragma unroll
    for (int j = 0; j < 4; ++j) acc[j] = 0ull;

    const float* mb_b = mb + ((size_t)b * S_ + s_tile) * DM_;
    const float* u_b = g_ut + (size_t)b * DM_ * H_;
    if (t < H_) s_Z[t] = 0.f;

    for (int kc = 0; kc < DM_ / KC3; ++kc) {
        __syncthreads();
        // stage mb tile: 64 rows x 32 floats (4 float4 per thread)
#pragma unroll
        for (int i = 0; i < 4; ++i) {
            int idx = i * 128 + t;
            int row = idx >> 3, f4 = idx & 7;
            float4 v = *reinterpret_cast<const float4*>(
                mb_b + (size_t)row * DM_ + kc * KC3 + f4 * 4);
            mb_s[row][f4 * 4 + 0] = v.x;
            mb_s[row][f4 * 4 + 1] = v.y;
            mb_s[row][f4 * 4 + 2] = v.z;
            mb_s[row][f4 * 4 + 3] = v.w;
        }
        // stage u chunk: 32 m x 16 h (coalesced, conflict-free)
#pragma unroll
        for (int i = 0; i < 4; ++i) {
            int idx = i * 128 + t;
            u_s[idx >> 4][idx & 15] = u_b[(size_t)(kc * KC3 + (idx >> 4)) * H_ + (idx & 15)];
        }
        __syncthreads();
#pragma unroll
        for (int k = 0; k < KC3; ++k) {
            ulonglong2 u01 = *reinterpret_cast<const ulonglong2*>(&u_s[k][h0]);
            ulonglong2 u23 = *reinterpret_cast<const ulonglong2*>(&u_s[k][h0 + 4]);
            float mv = mb_s[s_loc][k];
            u64 d = pack2(mv, mv);
            ffma2(acc[0], u01.x, d);
            ffma2(acc[1], u01.y, d);
            ffma2(acc[2], u23.x, d);
            ffma2(acc[3], u23.y, d);
        }
    }

    // epilogue: mask -> exp -> store e (coalesced per h row), local Z
    int s = s_tile + s_loc;
    bool msk = (mask[(size_t)b * S_ + s] != 0);
    float zp[8];
#pragma unroll
    for (int j = 0; j < 4; ++j) {
        float lo, hi;
        unpack2(acc[j], lo, hi);
        float e0 = msk ? 0.f : expf(lo);
        float e1 = msk ? 0.f : expf(hi);
        attn[(size_t)(b * H_ + h0 + j * 2 + 0) * S_ + s] = e0;
        attn[(size_t)(b * H_ + h0 + j * 2 + 1) * S_ + s] = e1;
        zp[j * 2] = e0;
        zp[j * 2 + 1] = e1;
    }
    // warp-level reduce over the 16 s-lanes sharing each h group, then smem atomic
#pragma unroll
    for (int j = 0; j < 8; ++j) {
#pragma unroll
        for (int off = 8; off > 0; off >>= 1)
            zp[j] += __shfl_down_sync(0xFFFFFFFFu, zp[j], off);
    }
    if ((l & 15) == 0) {
#pragma unroll
        for (int j = 0; j < 8; ++j) atomicAdd(&s_Z[h0 + j], zp[j]);
    }
    __syncthreads();
    if (t < H_) atomicAdd(&g_Z[b * H_ + t], s_Z[t]);
}

// ============================================================
// Kernel 4: normalize attn rows by Z. grid B*H, block 256
// ============================================================
__global__ __launch_bounds__(256) void k_norm(float* __restrict__ attn) {
    int bh = blockIdx.x;
    float inv = 1.f / g_Z[bh];
    float4* row = reinterpret_cast<float4*>(attn + (size_t)bh * S_);
#pragma unroll
    for (int i = 0; i < 4; ++i) {
        float4 v = row[threadIdx.x + i * 256];
        v.x *= inv; v.y *= inv; v.z *= inv; v.w *= inv;
        row[threadIdx.x + i * 256] = v;
    }
}

// ============================================================
// Kernel 5: c[b,h,m] += sum_s attn[b,h,s]*mb[b,s,m]
// MT=64, block 128, thread = 8 m x 1 h. grid (8, 16, B) = 2048 CTAs.
// Static smem ~26KB.
// ============================================================
#define SC5 32
#define MT5 64
#define P5 68
__global__ __launch_bounds__(128) void k_ctxacc(const float* __restrict__ mb,
                                                const float* __restrict__ attn) {
    __shared__ __align__(16) float mb_s[SC5][P5];   // [s][m], pitch 68
    __shared__ float a_s[256][H_ + 1];              // [s][h], pitch 17

    int m_base = blockIdx.x * MT5;
    int s_base = blockIdx.y * 256;
    int b = blockIdx.z;
    int t = threadIdx.x, w = t >> 5, l = t & 31;
    int m_loc = (w & 1) * 32 + (l & 3) * 8;         // 8 consecutive m
    int h = (w >> 1) * 8 + (l >> 2);                // single h

    const float* mb_b = mb + ((size_t)b * S_ + s_base) * DM_ + m_base;
    const float* a_b = attn + (size_t)b * H_ * S_ + s_base;

    // stage attn for this s-range: 256 s x 16 h (coalesced)
#pragma unroll
    for (int i = 0; i < 32; ++i) {
        int idx = i * 128 + t;
        a_s[idx & 255][idx >> 8] = a_b[(size_t)(idx >> 8) * S_ + (idx & 255)];
    }

    u64 acc[4];
#pragma unroll
    for (int j = 0; j < 4; ++j) acc[j] = 0ull;

    for (int ch = 0; ch < 8; ++ch) {
        __syncthreads();
        // stage mb chunk: 32 s x 64 m (4 float4 per thread)
#pragma unroll
        for (int i = 0; i < 4; ++i) {
            int idx = i * 128 + t;
            int row = idx >> 4, f4 = idx & 15;
            float4 v = *reinterpret_cast<const float4*>(
                mb_b + (size_t)(ch * 32 + row) * DM_ + f4 * 4);
            *reinterpret_cast<float4*>(&mb_s[row][f4 * 4]) = v;
        }
        __syncthreads();
#pragma unroll
        for (int k = 0; k < SC5; ++k) {
            ulonglong2 m01 = *reinterpret_cast<const ulonglong2*>(&mb_s[k][m_loc]);
            ulonglong2 m23 = *reinterpret_cast<const ulonglong2*>(&mb_s[k][m_loc + 4]);
            float a = a_s[ch * 32 + k][h];
            u64 d = pack2(a, a);
            ffma2(acc[0], m01.x, d);
            ffma2(acc[1], m01.y, d);
            ffma2(acc[2], m23.x, d);
            ffma2(acc[3], m23.y, d);
        }
    }
    float* dst = g_c + (size_t)(b * H_ + h) * DM_ + m_base + m_loc;
#pragma unroll
    for (int j = 0; j < 4; ++j) {
        float x0, x1;
        unpack2(acc[j], x0, x1);
        atomicAdd(dst + j * 2 + 0, x0);
        atomicAdd(dst + j * 2 + 1, x1);
    }
}

// ============================================================
// Kernel 6: context[b,h*64+d] += sum_m c[b,h,m]*Wv[m,h*64+d]
// Wv staged once, reused by all b. grid (H, 8), block 256
// ============================================================
__global__ __launch_bounds__(256) void k_ctx(const float* __restrict__ Wv,
                                             float* __restrict__ out) {
    __shared__ float wv_s[64][65];
    __shared__ float c_s[B_][64];
    int h = blockIdx.x;
    int m0 = blockIdx.y * 64;
    int t = threadIdx.x;
#pragma unroll
    for (int i = 0; i < 16; ++i) {
        int idx = i * 256 + t;
        wv_s[idx >> 6][idx & 63] = Wv[(size_t)(m0 + (idx >> 6)) * DO_ + h * D_ + (idx & 63)];
    }
#pragma unroll
    for (int i = 0; i < 4; ++i) {
        int idx = i * 256 + t;
        c_s[idx >> 6][idx & 63] = g_c[(size_t)((idx >> 6) * H_ + h) * DM_ + m0 + (idx & 63)];
    }
    __syncthreads();
    int d = t & 63, bg = t >> 6;
    float acc[4] = {0.f, 0.f, 0.f, 0.f};
#pragma unroll 8
    for (int mm = 0; mm < 64; ++mm) {
        float wv = wv_s[mm][d];
#pragma unroll
        for (int j = 0; j < 4; ++j) acc[j] = fmaf(c_s[bg + j * 4][mm], wv, acc[j]);
    }
#pragma unroll
    for (int j = 0; j < 4; ++j)
        atomicAdd(&out[(size_t)(bg + j * 4) * DO_ + h * D_ + d], acc[j]);
}

// ============================================================
extern "C" void kernel_launch(void* const* d_in, const int* in_sizes, int n_in,
                              void* d_out, int out_size) {
    const float* src = (const float*)d_in[0];
    const float* mb = (const float*)d_in[1];
    const float* Wq = (const float*)d_in[2];
    const float* Wk = (const float*)d_in[3];
    const float* Wv = (const float*)d_in[4];
    const int* mask = (const int*)d_in[5];
    float* out = (float*)d_out;
    float* attn = out + B_ * DO_;  // context first, then attn [B,H,S]

    k_zero<<<512, 256>>>(out);
    k_qproj<<<dim3(DO_ / 256, DQ_ / 64), 256>>>(src, Wq);
    k_uproj<<<B_ * H_, 256>>>(Wk);
    k_scores<<<dim3(S_ / TS3, B_), 128>>>(mb, attn, mask);
    k_norm<<<B_ * H_, 256>>>(attn);
    k_ctxacc<<<dim3(DM_ / MT5, S_ / 256, B_), 128>>>(mb, attn);
    k_ctx<<<dim3(H_, DM_ / 64), 256>>>(Wv, out);
}

// round 13
// speedup vs baseline: 1.1885x; 1.1885x over previous
#include <cuda_runtime.h>
#include <cstdint>
#include <math.h>

#define B_ 16
#define S_ 4096
#define DQ_ 1024
#define DM_ 512
#define DO_ 1024
#define H_ 16
#define D_ 64

typedef unsigned long long u64;

// -------- scratch (no allocs allowed) --------
__device__ float g_q[B_ * DO_];          // scaled query projections [b][h*64+d]
__device__ float g_ut[B_ * DM_ * H_];    // folded key proj, TRANSPOSED: [b][m][h]
__device__ float g_c[B_ * H_ * DM_];     // e-weighted mb sums [b][h][m] (unnormalized)
__device__ float g_Z[B_ * H_];           // softmax denominators

// -------- packed fp32x2 helpers --------
__device__ __forceinline__ u64 pack2(float lo, float hi) {
    u64 r; asm("mov.b64 %0, {%1,%2};" : "=l"(r) : "f"(lo), "f"(hi)); return r;
}
__device__ __forceinline__ void unpack2(u64 v, float& lo, float& hi) {
    asm("mov.b64 {%0,%1}, %2;" : "=f"(lo), "=f"(hi) : "l"(v));
}
__device__ __forceinline__ void ffma2(u64& d, u64 a, u64 b) {
    asm("fma.rn.f32x2 %0, %1, %2, %3;" : "=l"(d) : "l"(a), "l"(b), "l"(d));
}
__device__ __forceinline__ u64 add2(u64 a, u64 b) {
    u64 r; asm("add.rn.f32x2 %0, %1, %2;" : "=l"(r) : "l"(a), "l"(b)); return r;
}
__device__ __forceinline__ u64 shflx64(u64 v, int m) {
    return __shfl_xor_sync(0xFFFFFFFFu, v, m);
}

// ============================================================
// Kernel 0: zero accumulators. grid 512, block 256
// ============================================================
__global__ __launch_bounds__(256) void k_zero(float* __restrict__ out) {
    int i = blockIdx.x * 256 + threadIdx.x;
    if (i < B_ * DO_) { g_q[i] = 0.f; out[i] = 0.f; }
    if (i < B_ * H_ * DM_) g_c[i] = 0.f;
    if (i < B_ * H_) g_Z[i] = 0.f;
}

// ============================================================
// Kernel 1: q partial, Wq read once. grid (4,16), block 256
// ============================================================
__global__ __launch_bounds__(256) void k_qproj(const float* __restrict__ src,
                                               const float* __restrict__ Wq) {
    __shared__ float s_src[B_][64];
    int t = threadIdx.x;
    int o = blockIdx.x * 256 + t;
    int k0 = blockIdx.y * 64;
#pragma unroll
    for (int i = 0; i < 4; ++i) {
        int idx = i * 256 + t;
        s_src[idx >> 6][idx & 63] = src[(size_t)(idx >> 6) * DQ_ + k0 + (idx & 63)];
    }
    __syncthreads();
    float acc[B_];
#pragma unroll
    for (int b = 0; b < B_; ++b) acc[b] = 0.f;
#pragma unroll 4
    for (int k = 0; k < 64; ++k) {
        float wq = Wq[(size_t)(k0 + k) * DO_ + o];
#pragma unroll
        for (int b = 0; b < B_; ++b) acc[b] = fmaf(s_src[b][k], wq, acc[b]);
    }
#pragma unroll
    for (int b = 0; b < B_; ++b) atomicAdd(&g_q[b * DO_ + o], acc[b] * 0.125f);
}

// ============================================================
// Kernel 2: u[b,h,m] = sum_d Wk[m,h*64+d]*q[b,h,d], stored [b][m][h]
// grid B*H, block 256
// ============================================================
__global__ __launch_bounds__(256) void k_uproj(const float* __restrict__ Wk) {
    int bh = blockIdx.x;
    int b = bh >> 4, h = bh & 15;
    __shared__ float s_q[D_];
    if (threadIdx.x < D_) s_q[threadIdx.x] = g_q[b * DO_ + h * D_ + threadIdx.x];
    __syncthreads();
    for (int m = threadIdx.x; m < DM_; m += 256) {
        const float4* w = reinterpret_cast<const float4*>(Wk + (size_t)m * DO_ + h * D_);
        float acc = 0.f;
#pragma unroll
        for (int d4 = 0; d4 < D_ / 4; ++d4) {
            float4 wv = w[d4];
            acc = fmaf(wv.x, s_q[d4 * 4 + 0], acc);
            acc = fmaf(wv.y, s_q[d4 * 4 + 1], acc);
            acc = fmaf(wv.z, s_q[d4 * 4 + 2], acc);
            acc = fmaf(wv.w, s_q[d4 * 4 + 3], acc);
        }
        g_ut[((size_t)b * DM_ + m) * H_ + h] = acc;
    }
}

// ============================================================
// Kernel 3: e[b,h,s] = exp(score) (masked->0), Z accumulated.
// TS=128 s/CTA, block 128. Thread = 4s x 16h, k-split 4 in warp.
// grid (32, B) = 512 CTAs. smem ~37.4KB.
// ============================================================
#define TS3 128
#define KC3 64
__global__ __launch_bounds__(128, 4) void k_scores(const float* __restrict__ mb,
                                                   float* __restrict__ attn,
                                                   const int* __restrict__ mask) {
    __shared__ __align__(16) float u_s[KC3][H_];   // 4KB
    __shared__ float mb_s[TS3][65];                // 33.3KB, scalar access
    __shared__ float s_Z[H_];

    int b = blockIdx.y, s_tile = blockIdx.x * TS3;
    int t = threadIdx.x, w = t >> 5, l = t & 31;
    int sg = l & 7, kg = l >> 3;
    int s0 = w * 32 + sg * 4;                      // 4 consecutive s

    const float* mb_b = mb + ((size_t)b * S_ + s_tile) * DM_;
    const float* u_b = g_ut + (size_t)b * DM_ * H_;
    if (t < H_) s_Z[t] = 0.f;

    u64 acc[4][8];                                 // [s j][h pair]
#pragma unroll
    for (int j = 0; j < 4; ++j)
#pragma unroll
        for (int p = 0; p < 8; ++p) acc[j][p] = 0ull;

    for (int ch = 0; ch < DM_ / KC3; ++ch) {
        __syncthreads();
        // stage mb: 128 rows x 64 floats. 8 lanes/row -> coalesced 128B.
#pragma unroll
        for (int i = 0; i < 16; ++i) {
            int f4 = (l & 7) + (i & 1) * 8;
            int row = w * 4 + (l >> 3) + (i >> 1) * 16;
            float4 v = *reinterpret_cast<const float4*>(
                mb_b + (size_t)row * DM_ + ch * KC3 + f4 * 4);
            mb_s[row][f4 * 4 + 0] = v.x;
            mb_s[row][f4 * 4 + 1] = v.y;
            mb_s[row][f4 * 4 + 2] = v.z;
            mb_s[row][f4 * 4 + 3] = v.w;
        }
        // stage u chunk: 64 k x 16 h (float4, coalesced, conflict-free)
#pragma unroll
        for (int i = 0; i < 2; ++i) {
            int fidx = i * 128 + t;
            int k = fidx >> 2, h4 = fidx & 3;
            float4 v = *reinterpret_cast<const float4*>(
                u_b + (size_t)(ch * KC3 + k) * H_ + h4 * 4);
            *reinterpret_cast<float4*>(&u_s[k][h4 * 4]) = v;
        }
        __syncthreads();
#pragma unroll
        for (int ki = 0; ki < 16; ++ki) {
            int kk = ki * 4 + kg;
            ulonglong2 uA = *reinterpret_cast<const ulonglong2*>(&u_s[kk][0]);
            ulonglong2 uB = *reinterpret_cast<const ulonglong2*>(&u_s[kk][4]);
            ulonglong2 uC = *reinterpret_cast<const ulonglong2*>(&u_s[kk][8]);
            ulonglong2 uD = *reinterpret_cast<const ulonglong2*>(&u_s[kk][12]);
#pragma unroll
            for (int j = 0; j < 4; ++j) {
                float mv = mb_s[s0 + j][kk];
                u64 d = pack2(mv, mv);
                ffma2(acc[j][0], uA.x, d); ffma2(acc[j][1], uA.y, d);
                ffma2(acc[j][2], uB.x, d); ffma2(acc[j][3], uB.y, d);
                ffma2(acc[j][4], uC.x, d); ffma2(acc[j][5], uC.y, d);
                ffma2(acc[j][6], uD.x, d); ffma2(acc[j][7], uD.y, d);
            }
        }
    }

    // k-split reduction across lane-groups (xor 8, 16), packed adds
#pragma unroll
    for (int j = 0; j < 4; ++j)
#pragma unroll
        for (int p = 0; p < 8; ++p) {
            u64 v = acc[j][p];
            v = add2(v, shflx64(v, 8));
            v = add2(v, shflx64(v, 16));
            acc[j][p] = v;
        }

    // epilogue: lane-group kg handles h = 4kg..4kg+3 for its 4 s
    int4 mk = *reinterpret_cast<const int4*>(mask + (size_t)b * S_ + s_tile + s0);
    int mki[4] = {mk.x, mk.y, mk.z, mk.w};
    float e[4][4];                                 // [hl][j]
    float zh[4] = {0.f, 0.f, 0.f, 0.f};
#pragma unroll
    for (int j = 0; j < 4; ++j) {
#pragma unroll
        for (int hl = 0; hl < 4; ++hl) {
            float lo, hi;
            unpack2(acc[j][kg * 2 + (hl >> 1)], lo, hi);
            float sc = (hl & 1) ? hi : lo;
            float ev = mki[j] ? 0.f : __expf(sc);
            e[hl][j] = ev;
            zh[hl] += ev;
        }
    }
#pragma unroll
    for (int hl = 0; hl < 4; ++hl) {
        float4 v4 = make_float4(e[hl][0], e[hl][1], e[hl][2], e[hl][3]);
        *reinterpret_cast<float4*>(
            attn + (size_t)(b * H_ + kg * 4 + hl) * S_ + s_tile + s0) = v4;
        zh[hl] += __shfl_xor_sync(0xFFFFFFFFu, zh[hl], 1);
        zh[hl] += __shfl_xor_sync(0xFFFFFFFFu, zh[hl], 2);
        zh[hl] += __shfl_xor_sync(0xFFFFFFFFu, zh[hl], 4);
    }
    if (sg == 0) {
#pragma unroll
        for (int hl = 0; hl < 4; ++hl) atomicAdd(&s_Z[kg * 4 + hl], zh[hl]);
    }
    __syncthreads();
    if (t < H_) atomicAdd(&g_Z[b * H_ + t], s_Z[t]);
}

// ============================================================
// Kernel 4: c[b,h,m] += sum_s e[b,h,s]*mb[b,s,m]  (unnormalized e!)
// MT=128 m/CTA, 256 s/CTA, s-chunks of 32. Thread = 4m x 16h,
// s-split 4 in warp. grid (4, 16, B) = 1024 CTAs. smem ~37KB.
// ============================================================
#define MT5 128
#define SC5 32
__global__ __launch_bounds__(128, 4) void k_ctxacc(const float* __restrict__ mb,
                                                   const float* __restrict__ attn) {
    __shared__ __align__(16) float a_s[256][20];   // 20KB, pitch 20 (LDS.128 ok)
    __shared__ float mb_s[SC5][129];               // 16.5KB, scalar access
    int m_base = blockIdx.x * MT5;
    int s_base = blockIdx.y * 256;
    int b = blockIdx.z;
    int t = threadIdx.x, w = t >> 5, l = t & 31;
    int sg = l >> 3;
    int m0 = w * 32 + (l & 7) * 4;                 // 4 consecutive m

    const float* mb_b = mb + ((size_t)b * S_ + s_base) * DM_ + m_base;
    const float* a_b = attn + (size_t)b * H_ * S_ + s_base;

    // stage attn (e) for this s-range: 256 s x 16 h, gmem-coalesced
#pragma unroll
    for (int i = 0; i < 32; ++i) {
        int idx = i * 128 + t;
        a_s[idx & 255][idx >> 8] = a_b[(size_t)(idx >> 8) * S_ + (idx & 255)];
    }

    u64 acc[4][8];                                 // [m j][h pair]
#pragma unroll
    for (int j = 0; j < 4; ++j)
#pragma unroll
        for (int p = 0; p < 8; ++p) acc[j][p] = 0ull;

    for (int sc = 0; sc < 256 / SC5; ++sc) {
        __syncthreads();
        // stage mb chunk: 32 rows(s) x 128 m. 8 lanes/row 128B coalesced;
        // STS banks (l>>3)+4*(l&7)+j distinct -> conflict-free.
#pragma unroll
        for (int i = 0; i < 8; ++i) {
            int f8 = (l & 7) + (i & 3) * 8;
            int row = (i >> 2) * 16 + w * 4 + (l >> 3);
            float4 v = *reinterpret_cast<const float4*>(
                mb_b + (size_t)(sc * SC5 + row) * DM_ + f8 * 4);
            mb_s[row][f8 * 4 + 0] = v.x;
            mb_s[row][f8 * 4 + 1] = v.y;
            mb_s[row][f8 * 4 + 2] = v.z;
            mb_s[row][f8 * 4 + 3] = v.w;
        }
        __syncthreads();
#pragma unroll
        for (int ki = 0; ki < 8; ++ki) {
            int ss = ki * 4 + sg;
            int sa = sc * SC5 + ss;
            ulonglong2 aA = *reinterpret_cast<const ulonglong2*>(&a_s[sa][0]);
            ulonglong2 aB = *reinterpret_cast<const ulonglong2*>(&a_s[sa][4]);
            ulonglong2 aC = *reinterpret_cast<const ulonglong2*>(&a_s[sa][8]);
            ulonglong2 aD = *reinterpret_cast<const ulonglong2*>(&a_s[sa][12]);
#pragma unroll
            for (int j = 0; j < 4; ++j) {
                float mv = mb_s[ss][m0 + j];
                u64 d = pack2(mv, mv);
                ffma2(acc[j][0], aA.x, d); ffma2(acc[j][1], aA.y, d);
                ffma2(acc[j][2], aB.x, d); ffma2(acc[j][3], aB.y, d);
                ffma2(acc[j][4], aC.x, d); ffma2(acc[j][5], aC.y, d);
                ffma2(acc[j][6], aD.x, d); ffma2(acc[j][7], aD.y, d);
            }
        }
    }

    // s-split reduction across lane-groups
#pragma unroll
    for (int j = 0; j < 4; ++j)
#pragma unroll
        for (int p = 0; p < 8; ++p) {
            u64 v = acc[j][p];
            v = add2(v, shflx64(v, 8));
            v = add2(v, shflx64(v, 16));
            acc[j][p] = v;
        }

    // lane-group sg writes h-slice 4sg..4sg+3 (16 atomics/thread)
#pragma unroll
    for (int hl = 0; hl < 4; ++hl) {
        int h = sg * 4 + hl;
        float* dst = g_c + (size_t)(b * H_ + h) * DM_ + m_base + m0;
#pragma unroll
        for (int j = 0; j < 4; ++j) {
            float lo, hi;
            unpack2(acc[j][sg * 2 + (hl >> 1)], lo, hi);
            atomicAdd(dst + j, (hl & 1) ? hi : lo);
        }
    }
}

// ============================================================
// Kernel 5: normalize attn rows by Z. grid B*H, block 256
// ============================================================
__global__ __launch_bounds__(256) void k_norm(float* __restrict__ attn) {
    int bh = blockIdx.x;
    float inv = 1.f / g_Z[bh];
    float4* row = reinterpret_cast<float4*>(attn + (size_t)bh * S_);
#pragma unroll
    for (int i = 0; i < 4; ++i) {
        float4 v = row[threadIdx.x + i * 256];
        v.x *= inv; v.y *= inv; v.z *= inv; v.w *= inv;
        row[threadIdx.x + i * 256] = v;
    }
}

// ============================================================
// Kernel 6: context[b,h*64+d] += (1/Z) * sum_m c[b,h,m]*Wv[m,h*64+d]
// Wv staged once, reused by all b. grid (H, 8), block 256
// ============================================================
__global__ __launch_bounds__(256) void k_ctx(const float* __restrict__ Wv,
                                             float* __restrict__ out) {
    __shared__ float wv_s[64][65];
    __shared__ float c_s[B_][64];
    __shared__ float iz_s[B_];
    int h = blockIdx.x;
    int m0 = blockIdx.y * 64;
    int t = threadIdx.x;
    if (t < B_) iz_s[t] = 1.f / g_Z[t * H_ + h];
#pragma unroll
    for (int i = 0; i < 16; ++i) {
        int idx = i * 256 + t;
        wv_s[idx >> 6][idx & 63] = Wv[(size_t)(m0 + (idx >> 6)) * DO_ + h * D_ + (idx & 63)];
    }
#pragma unroll
    for (int i = 0; i < 4; ++i) {
        int idx = i * 256 + t;
        c_s[idx >> 6][idx & 63] = g_c[(size_t)((idx >> 6) * H_ + h) * DM_ + m0 + (idx & 63)];
    }
    __syncthreads();
    int d = t & 63, bg = t >> 6;
    float acc[4] = {0.f, 0.f, 0.f, 0.f};
#pragma unroll 8
    for (int mm = 0; mm < 64; ++mm) {
        float wv = wv_s[mm][d];
#pragma unroll
        for (int j = 0; j < 4; ++j) acc[j] = fmaf(c_s[bg + j * 4][mm], wv, acc[j]);
    }
#pragma unroll
    for (int j = 0; j < 4; ++j)
        atomicAdd(&out[(size_t)(bg + j * 4) * DO_ + h * D_ + d],
                  acc[j] * iz_s[bg + j * 4]);
}

// ============================================================
extern "C" void kernel_launch(void* const* d_in, const int* in_sizes, int n_in,
                              void* d_out, int out_size) {
    const float* src = (const float*)d_in[0];
    const float* mb = (const float*)d_in[1];
    const float* Wq = (const float*)d_in[2];
    const float* Wk = (const float*)d_in[3];
    const float* Wv = (const float*)d_in[4];
    const int* mask = (const int*)d_in[5];
    float* out = (float*)d_out;
    float* attn = out + B_ * DO_;  // context first, then attn [B,H,S]

    k_zero<<<512, 256>>>(out);
    k_qproj<<<dim3(DO_ / 256, DQ_ / 64), 256>>>(src, Wq);
    k_uproj<<<B_ * H_, 256>>>(Wk);
    k_scores<<<dim3(S_ / TS3, B_), 128>>>(mb, attn, mask);
    k_ctxacc<<<dim3(DM_ / MT5, S_ / 256, B_), 128>>>(mb, attn);  // uses raw e
    k_norm<<<B_ * H_, 256>>>(attn);
    k_ctx<<<dim3(H_, DM_ / 64), 256>>>(Wv, out);
}